// round 3
// baseline (speedup 1.0000x reference)
#include <cuda_runtime.h>
#include <math.h>

// ---------------- problem dims ----------------
constexpr int Vv = 32000;
constexpr int C  = 1024;
constexpr int Hh = 16;
constexpr int E  = 8;
constexpr int Ll = 4;
constexpr int B  = 4;
constexpr int T  = 512;
constexpr int BT = B * T;          // 2048 tokens
constexpr int D  = C / Hh;         // 64

// ---------------- static scratch (no runtime alloc allowed) ----------------
__device__ float g_x   [BT * C];           // residual stream
__device__ float g_qkv [BT * 3 * C];       // qkv
__device__ float g_abuf[BT * C];           // attention output
__device__ float g_tmp [BT * C];           // proj out / final-LN out
__device__ float g_h   [BT * C];           // expert hidden
__device__ float g_y   [BT * C];           // expert output
__device__ float g_moe [BT * C];           // y[winner] per token
__device__ float g_esum[E * C];            // masked sums per expert
__device__ int   g_win [BT];
__device__ int   g_mask[BT];
__device__ int   g_cnt [E];

// ---------------- block reductions (256 threads assumed) ----------------
__device__ __forceinline__ float blk_sum(float v) {
    __shared__ float sh[8];
    __syncthreads();
    #pragma unroll
    for (int o = 16; o > 0; o >>= 1) v += __shfl_down_sync(0xffffffffu, v, o);
    if ((threadIdx.x & 31) == 0) sh[threadIdx.x >> 5] = v;
    __syncthreads();
    if (threadIdx.x == 0) {
        float t = 0.f;
        #pragma unroll
        for (int i = 0; i < 8; i++) t += sh[i];
        sh[0] = t;
    }
    __syncthreads();
    return sh[0];
}

// ---------------- embedding + positional encoding ----------------
__global__ void embed_kernel(const int* __restrict__ ids,
                             const float* __restrict__ emb,
                             float* __restrict__ x) {
    int t = blockIdx.x;                 // token 0..2047
    int pos = t & (T - 1);
    int id = ids[t];
    const float* erow = emb + (size_t)id * C;
    float* xrow = x + (size_t)t * C;
    const float nl = -9.210340371976184f / (float)C;  // -ln(10000)/C
    #pragma unroll
    for (int i = 0; i < 4; i++) {
        int c = threadIdx.x + i * 256;
        int i2 = c & ~1;
        float freq = expf((float)i2 * nl);
        float val = (float)pos * freq;
        float pe = (c & 1) ? cosf(val) : sinf(val);
        xrow[c] = erow[c] + pe;
    }
}

// ---------------- generic SGEMM: C = act(A @ opB + bias) ----------------
template<bool TRANSB, bool ACT_GELU>
__global__ void __launch_bounds__(256)
sgemm_kernel(const float* __restrict__ A,
             const float* __restrict__ Bm,
             const float* __restrict__ bias,
             float* __restrict__ Cm,
             int M, int N, int K,
             const int* __restrict__ winner, int eid,
             float* __restrict__ C2) {
    __shared__ float As[8][128];
    __shared__ float Bs[8][128];
    int tid = threadIdx.x;
    int row0 = blockIdx.y * 128;
    int col0 = blockIdx.x * 128;
    int ty = tid >> 4, tx = tid & 15;

    float acc[8][8];
    #pragma unroll
    for (int i = 0; i < 8; i++)
        #pragma unroll
        for (int j = 0; j < 8; j++) acc[i][j] = 0.f;

    const int ar = tid >> 1, ac = (tid & 1) * 4;
    const float* Aptr = A + (size_t)(row0 + ar) * K + ac;

    for (int kt = 0; kt < K; kt += 8) {
        float4 av = *(const float4*)(Aptr + kt);
        As[ac + 0][ar] = av.x; As[ac + 1][ar] = av.y;
        As[ac + 2][ar] = av.z; As[ac + 3][ar] = av.w;
        if (TRANSB) {
            int br = tid >> 1, bc = (tid & 1) * 4;
            float4 bv = *(const float4*)(Bm + (size_t)(col0 + br) * K + kt + bc);
            Bs[bc + 0][br] = bv.x; Bs[bc + 1][br] = bv.y;
            Bs[bc + 2][br] = bv.z; Bs[bc + 3][br] = bv.w;
        } else {
            int bk = tid >> 5, bn = (tid & 31) * 4;
            float4 bv = *(const float4*)(Bm + (size_t)(kt + bk) * N + col0 + bn);
            *(float4*)&Bs[bk][bn] = bv;
        }
        __syncthreads();
        #pragma unroll
        for (int k = 0; k < 8; k++) {
            float ra[8], rb[8];
            float4 a0 = *(const float4*)&As[k][ty * 8];
            float4 a1 = *(const float4*)&As[k][ty * 8 + 4];
            float4 b0 = *(const float4*)&Bs[k][tx * 8];
            float4 b1 = *(const float4*)&Bs[k][tx * 8 + 4];
            ra[0] = a0.x; ra[1] = a0.y; ra[2] = a0.z; ra[3] = a0.w;
            ra[4] = a1.x; ra[5] = a1.y; ra[6] = a1.z; ra[7] = a1.w;
            rb[0] = b0.x; rb[1] = b0.y; rb[2] = b0.z; rb[3] = b0.w;
            rb[4] = b1.x; rb[5] = b1.y; rb[6] = b1.z; rb[7] = b1.w;
            #pragma unroll
            for (int i = 0; i < 8; i++)
                #pragma unroll
                for (int j = 0; j < 8; j++)
                    acc[i][j] += ra[i] * rb[j];
        }
        __syncthreads();
    }

    #pragma unroll
    for (int i = 0; i < 8; i++) {
        int r = row0 + ty * 8 + i;
        int wsel = (winner != nullptr) ? winner[r] : -1;
        #pragma unroll
        for (int j = 0; j < 8; j++) {
            int c = col0 + tx * 8 + j;
            float v = acc[i][j];
            if (bias) v += bias[c];
            if (ACT_GELU) v = 0.5f * v * (1.0f + erff(v * 0.70710678118654752f));
            Cm[(size_t)r * N + c] = v;
            if (winner != nullptr && wsel == eid) C2[(size_t)r * N + c] = v;
        }
    }
}

// ---------------- fused attention: out = softmax(QK^T/8) V ----------------
// One block per (b, h, 64-row t-tile). Full score rows (T=512) live in smem.
constexpr int SSTRIDE = 513;
constexpr int ATTN_SMEM = (64 * SSTRIDE + 2 * 64 * 68) * 4;   // 166,144 B

__global__ void __launch_bounds__(256)
attn_fused(const float* __restrict__ qkv, float* __restrict__ abuf) {
    extern __shared__ float sm[];
    float* Sc = sm;                         // [64][SSTRIDE]
    float* Qs = sm + 64 * SSTRIDE;          // [64][68]  (transposed: [d][t])
    float* KV = Qs + 64 * 68;               // [64][68]

    int bh = blockIdx.y;
    int b = bh >> 4, h = bh & 15;
    int t0 = blockIdx.x * 64;
    const float* qb = qkv + (size_t)b * T * (3 * C) + h * D;
    const float* kb = qb + C;
    const float* vb = qb + 2 * C;

    int tid = threadIdx.x;
    int row = tid >> 2, cb = (tid & 3) * 16;
    int ty = tid >> 4, tx = tid & 15;

    // load Q tile transposed [d][t]
    #pragma unroll
    for (int j = 0; j < 4; j++) {
        float4 q4 = *(const float4*)(qb + (size_t)(t0 + row) * (3 * C) + cb + j * 4);
        Qs[(cb + j * 4 + 0) * 68 + row] = q4.x;
        Qs[(cb + j * 4 + 1) * 68 + row] = q4.y;
        Qs[(cb + j * 4 + 2) * 68 + row] = q4.z;
        Qs[(cb + j * 4 + 3) * 68 + row] = q4.w;
    }

    // ---- scores ----
    for (int s0 = 0; s0 < T; s0 += 64) {
        __syncthreads();
        #pragma unroll
        for (int j = 0; j < 4; j++) {
            float4 k4 = *(const float4*)(kb + (size_t)(s0 + row) * (3 * C) + cb + j * 4);
            KV[(cb + j * 4 + 0) * 68 + row] = k4.x;
            KV[(cb + j * 4 + 1) * 68 + row] = k4.y;
            KV[(cb + j * 4 + 2) * 68 + row] = k4.z;
            KV[(cb + j * 4 + 3) * 68 + row] = k4.w;
        }
        __syncthreads();
        float acc[4][4] = {};
        #pragma unroll 4
        for (int d = 0; d < 64; d++) {
            float a_[4], b_[4];
            #pragma unroll
            for (int i = 0; i < 4; i++) a_[i] = Qs[d * 68 + ty * 4 + i];
            #pragma unroll
            for (int j = 0; j < 4; j++) b_[j] = KV[d * 68 + tx * 4 + j];
            #pragma unroll
            for (int i = 0; i < 4; i++)
                #pragma unroll
                for (int j = 0; j < 4; j++) acc[i][j] += a_[i] * b_[j];
        }
        #pragma unroll
        for (int i = 0; i < 4; i++)
            #pragma unroll
            for (int j = 0; j < 4; j++)
                Sc[(ty * 4 + i) * SSTRIDE + s0 + tx * 4 + j] = acc[i][j] * 0.125f;
    }
    __syncthreads();

    // ---- softmax: each warp handles one row (8 rows per pass) ----
    int warp = tid >> 5, lane = tid & 31;
    #pragma unroll
    for (int it = 0; it < 8; it++) {
        int r = it * 8 + warp;
        float* srow = Sc + r * SSTRIDE;
        float v[16];
        float m = -1e30f;
        #pragma unroll
        for (int k = 0; k < 16; k++) { v[k] = srow[lane + 32 * k]; m = fmaxf(m, v[k]); }
        #pragma unroll
        for (int o = 16; o > 0; o >>= 1) m = fmaxf(m, __shfl_xor_sync(0xffffffffu, m, o));
        float s = 0.f;
        #pragma unroll
        for (int k = 0; k < 16; k++) { v[k] = expf(v[k] - m); s += v[k]; }
        #pragma unroll
        for (int o = 16; o > 0; o >>= 1) s += __shfl_xor_sync(0xffffffffu, s, o);
        float inv = 1.0f / s;
        #pragma unroll
        for (int k = 0; k < 16; k++) srow[lane + 32 * k] = v[k] * inv;
    }

    // ---- PV ----
    float acc[4][4] = {};
    for (int s0 = 0; s0 < T; s0 += 64) {
        __syncthreads();
        #pragma unroll
        for (int j = 0; j < 4; j++) {
            float4 v4 = *(const float4*)(vb + (size_t)(s0 + row) * (3 * C) + cb + j * 4);
            *(float4*)&KV[row * 68 + cb + j * 4] = v4;   // [s][d]
        }
        __syncthreads();
        #pragma unroll 4
        for (int s = 0; s < 64; s++) {
            float a_[4], b_[4];
            #pragma unroll
            for (int i = 0; i < 4; i++) a_[i] = Sc[(ty * 4 + i) * SSTRIDE + s0 + s];
            #pragma unroll
            for (int j = 0; j < 4; j++) b_[j] = KV[s * 68 + tx * 4 + j];
            #pragma unroll
            for (int i = 0; i < 4; i++)
                #pragma unroll
                for (int j = 0; j < 4; j++) acc[i][j] += a_[i] * b_[j];
        }
    }
    #pragma unroll
    for (int i = 0; i < 4; i++)
        #pragma unroll
        for (int j = 0; j < 4; j++)
            abuf[((size_t)b * T + t0 + ty * 4 + i) * C + h * D + tx * 4 + j] = acc[i][j];
}

// ---------------- LayerNorm: out = LN(x [+ add]) ----------------
__global__ void __launch_bounds__(256)
add_ln(const float* __restrict__ x, const float* __restrict__ add,
       const float* __restrict__ g, const float* __restrict__ b,
       float* __restrict__ out) {
    int t = blockIdx.x;
    size_t base = (size_t)t * C;
    float v[4];
    #pragma unroll
    for (int i = 0; i < 4; i++) {
        int c = threadIdx.x + i * 256;
        v[i] = x[base + c] + (add ? add[base + c] : 0.f);
    }
    float mean = blk_sum(v[0] + v[1] + v[2] + v[3]) * (1.0f / C);
    float sq = 0.f;
    #pragma unroll
    for (int i = 0; i < 4; i++) { float d = v[i] - mean; sq += d * d; }
    float var = blk_sum(sq) * (1.0f / C);
    float rstd = rsqrtf(var + 1e-5f);
    #pragma unroll
    for (int i = 0; i < 4; i++) {
        int c = threadIdx.x + i * 256;
        out[base + c] = (v[i] - mean) * rstd * g[c] + b[c];
    }
}

// ---------------- router: logits -> top2, winner, mask, counts ----------------
__global__ void __launch_bounds__(256)
router_kernel(const float* __restrict__ x, const float* __restrict__ rw,
              const float* __restrict__ rb,
              int* __restrict__ win, int* __restrict__ maskb,
              int* __restrict__ cnt) {
    int t = blockIdx.x;
    int wid = threadIdx.x >> 5, lane = threadIdx.x & 31;
    const float* xr = x + (size_t)t * C;
    const float* w = rw + (size_t)wid * C;
    float s = 0.f;
    for (int c = lane; c < C; c += 32) s += xr[c] * w[c];
    #pragma unroll
    for (int o = 16; o > 0; o >>= 1) s += __shfl_down_sync(0xffffffffu, s, o);
    __shared__ float logits[E];
    if (lane == 0) logits[wid] = s + rb[wid];
    __syncthreads();
    if (threadIdx.x == 0) {
        int i0 = 0; float b0 = logits[0];
        #pragma unroll
        for (int e = 1; e < E; e++) if (logits[e] > b0) { b0 = logits[e]; i0 = e; }
        int i1 = -1; float b1 = -1e30f;
        #pragma unroll
        for (int e = 0; e < E; e++) if (e != i0 && logits[e] > b1) { b1 = logits[e]; i1 = e; }
        int wnr = i0 > i1 ? i0 : i1;
        win[t] = wnr;
        maskb[t] = (1 << i0) | (1 << i1);
        atomicAdd(&cnt[i0], 1);
        atomicAdd(&cnt[i1], 1);
    }
}

__global__ void zero_small(int* c, float* es) {
    if (blockIdx.x == 0 && threadIdx.x < E) c[threadIdx.x] = 0;
    for (int i = blockIdx.x * blockDim.x + threadIdx.x; i < E * C; i += gridDim.x * blockDim.x)
        es[i] = 0.f;
}

// ---------------- per-expert masked partial sum over token chunks ----------------
__global__ void __launch_bounds__(256)
expert_reduce(const float* __restrict__ y, const int* __restrict__ maskb,
              float* __restrict__ esum, int e) {
    int c = blockIdx.x * 256 + threadIdx.x;
    int t0 = blockIdx.y * 64;
    float s = 0.f;
    #pragma unroll 4
    for (int t = t0; t < t0 + 64; t++) {
        if ((maskb[t] >> e) & 1) s += y[(size_t)t * C + c];
    }
    atomicAdd(&esum[e * C + c], s);
}

// ---------------- MoE finalize + LN ----------------
__global__ void __launch_bounds__(256)
moe_ln(float* __restrict__ x, const float* __restrict__ moe,
       const float* __restrict__ esum, const int* __restrict__ win,
       const int* __restrict__ cnt, float inv_cache,
       const float* __restrict__ g, const float* __restrict__ b) {
    int t = blockIdx.x;
    size_t base = (size_t)t * C;
    int w = win[t];
    float cs = inv_cache / fmaxf((float)cnt[w], 1.0f);
    float v[4];
    #pragma unroll
    for (int i = 0; i < 4; i++) {
        int c = threadIdx.x + i * 256;
        v[i] = x[base + c] + moe[base + c] + esum[w * C + c] * cs;
    }
    float mean = blk_sum(v[0] + v[1] + v[2] + v[3]) * (1.0f / C);
    float sq = 0.f;
    #pragma unroll
    for (int i = 0; i < 4; i++) { float d = v[i] - mean; sq += d * d; }
    float var = blk_sum(sq) * (1.0f / C);
    float rstd = rsqrtf(var + 1e-5f);
    #pragma unroll
    for (int i = 0; i < 4; i++) {
        int c = threadIdx.x + i * 256;
        x[base + c] = (v[i] - mean) * rstd * g[c] + b[c];
    }
}

// ---------------- host launch ----------------
extern "C" void kernel_launch(void* const* d_in, const int* in_sizes, int n_in,
                              void* d_out, int out_size) {
    const int*   ids      = (const int*)  d_in[0];
    const float* emb      = (const float*)d_in[1];
    const float* qkv_w    = (const float*)d_in[2];
    const float* qkv_b    = (const float*)d_in[3];
    const float* out_w    = (const float*)d_in[4];
    const float* out_b    = (const float*)d_in[5];
    const float* ln1_g    = (const float*)d_in[6];
    const float* ln1_b    = (const float*)d_in[7];
    const float* router_w = (const float*)d_in[8];
    const float* router_b = (const float*)d_in[9];
    const float* w1       = (const float*)d_in[10];
    const float* b1       = (const float*)d_in[11];
    const float* w2       = (const float*)d_in[12];
    const float* b2       = (const float*)d_in[13];
    const float* ln2_g    = (const float*)d_in[14];
    const float* ln2_b    = (const float*)d_in[15];
    const float* lnf_g    = (const float*)d_in[16];
    const float* lnf_b    = (const float*)d_in[17];
    const float* head_w   = (const float*)d_in[18];
    float* out = (float*)d_out;

    float *dX, *dQKV, *dABUF, *dTMP, *dH, *dY, *dMOE, *dESUM;
    int *dWIN, *dMASK, *dCNT;
    cudaGetSymbolAddress((void**)&dX, g_x);
    cudaGetSymbolAddress((void**)&dQKV, g_qkv);
    cudaGetSymbolAddress((void**)&dABUF, g_abuf);
    cudaGetSymbolAddress((void**)&dTMP, g_tmp);
    cudaGetSymbolAddress((void**)&dH, g_h);
    cudaGetSymbolAddress((void**)&dY, g_y);
    cudaGetSymbolAddress((void**)&dMOE, g_moe);
    cudaGetSymbolAddress((void**)&dESUM, g_esum);
    cudaGetSymbolAddress((void**)&dWIN, g_win);
    cudaGetSymbolAddress((void**)&dMASK, g_mask);
    cudaGetSymbolAddress((void**)&dCNT, g_cnt);

    cudaFuncSetAttribute(attn_fused, cudaFuncAttributeMaxDynamicSharedMemorySize, ATTN_SMEM);

    embed_kernel<<<BT, 256>>>(ids, emb, dX);

    for (int l = 0; l < Ll; l++) {
        const float* qw = qkv_w + (size_t)l * 3 * C * C;
        const float* qb = qkv_b + (size_t)l * 3 * C;
        // QKV = X @ qkv_w^T + b    [2048, 3072]
        sgemm_kernel<true, false><<<dim3(3 * C / 128, BT / 128), 256>>>(
            dX, qw, qb, dQKV, BT, 3 * C, C, nullptr, 0, nullptr);

        attn_fused<<<dim3(T / 64, B * Hh), 256, ATTN_SMEM>>>(dQKV, dABUF);

        // proj
        sgemm_kernel<true, false><<<dim3(C / 128, BT / 128), 256>>>(
            dABUF, out_w + (size_t)l * C * C, out_b + (size_t)l * C, dTMP,
            BT, C, C, nullptr, 0, nullptr);
        add_ln<<<BT, 256>>>(dX, dTMP, ln1_g + (size_t)l * C, ln1_b + (size_t)l * C, dX);

        // router + zero accumulators
        zero_small<<<8, 1024>>>(dCNT, dESUM);
        router_kernel<<<BT, 256>>>(dX, router_w + (size_t)l * E * C,
                                   router_b + (size_t)l * E, dWIN, dMASK, dCNT);

        // experts (dense over all tokens, matching reference)
        for (int e = 0; e < E; e++) {
            const float* w1e = w1 + ((size_t)l * E + e) * C * C;
            const float* b1e = b1 + ((size_t)l * E + e) * C;
            const float* w2e = w2 + ((size_t)l * E + e) * C * C;
            const float* b2e = b2 + ((size_t)l * E + e) * C;
            sgemm_kernel<false, true><<<dim3(C / 128, BT / 128), 256>>>(
                dX, w1e, b1e, dH, BT, C, C, nullptr, 0, nullptr);
            sgemm_kernel<false, false><<<dim3(C / 128, BT / 128), 256>>>(
                dH, w2e, b2e, dY, BT, C, C, dWIN, e, dMOE);
            expert_reduce<<<dim3(C / 256, BT / 64), 256>>>(dY, dMASK, dESUM, e);
        }

        float inv_cache = 1.0f / (float)(128 - 8 * l);
        moe_ln<<<BT, 256>>>(dX, dMOE, dESUM, dWIN, dCNT, inv_cache,
                            ln2_g + (size_t)l * C, ln2_b + (size_t)l * C);
    }

    // final LN + head
    add_ln<<<BT, 256>>>(dX, nullptr, lnf_g, lnf_b, dTMP);
    sgemm_kernel<true, false><<<dim3(Vv / 128, BT / 128), 256>>>(
        dTMP, head_w, nullptr, out, BT, Vv, C, nullptr, 0, nullptr);
}

// round 5
// speedup vs baseline: 2.5196x; 2.5196x over previous
#include <cuda_runtime.h>
#include <cuda_bf16.h>
#include <math.h>

// ---------------- problem dims ----------------
constexpr int Vv = 32000;
constexpr int C  = 1024;
constexpr int Hh = 16;
constexpr int E  = 8;
constexpr int Ll = 4;
constexpr int B  = 4;
constexpr int T  = 512;
constexpr int BT = B * T;          // 2048 tokens
constexpr int D  = C / Hh;         // 64

constexpr int NQKVW = Ll * 3 * C * C;   // 12,582,912
constexpr int NOUTW = Ll * C * C;       //  4,194,304
constexpr int NW    = Ll * E * C * C;   // 33,554,432
constexpr int NHEAD = Vv * C;           // 32,768,000

// ---------------- static scratch ----------------
__device__ float g_x   [BT * C];
__device__ float g_qkv [BT * 3 * C];
__device__ float g_abuf[BT * C];
__device__ float g_tmp [BT * C];
__device__ float g_h   [E * BT * C];
__device__ float g_y   [E * BT * C];
__device__ float g_moe [BT * C];
__device__ float g_esum[E * C];
__device__ int   g_win [BT];
__device__ int   g_mask[BT];
__device__ int   g_cnt [E];

// split-bf16 weights ([N,K] layout, hi + lo)
__device__ __nv_bfloat16 s_qkvw_h[NQKVW], s_qkvw_l[NQKVW];
__device__ __nv_bfloat16 s_outw_h[NOUTW], s_outw_l[NOUTW];
__device__ __nv_bfloat16 s_w1_h  [NW],    s_w1_l  [NW];
__device__ __nv_bfloat16 s_w2_h  [NW],    s_w2_l  [NW];
__device__ __nv_bfloat16 s_head_h[NHEAD], s_head_l[NHEAD];

// ---------------- helpers ----------------
__device__ __forceinline__ float gelu_f(float v) {
    return 0.5f * v * (1.0f + erff(v * 0.70710678118654752f));
}

__device__ __forceinline__ void mma_bf16(float* c, const unsigned* a, const unsigned* b) {
    asm volatile(
        "mma.sync.aligned.m16n8k16.row.col.f32.bf16.bf16.f32 "
        "{%0,%1,%2,%3}, {%4,%5,%6,%7}, {%8,%9}, {%0,%1,%2,%3};\n"
        : "+f"(c[0]), "+f"(c[1]), "+f"(c[2]), "+f"(c[3])
        : "r"(a[0]), "r"(a[1]), "r"(a[2]), "r"(a[3]), "r"(b[0]), "r"(b[1]));
}

__device__ __forceinline__ unsigned pack_bf16(__nv_bfloat16 a, __nv_bfloat16 b) {
    return (unsigned)__bfloat16_as_ushort(a) | ((unsigned)__bfloat16_as_ushort(b) << 16);
}

__device__ __forceinline__ void split2(float x, __nv_bfloat16& h, __nv_bfloat16& l) {
    h = __float2bfloat16(x);
    l = __float2bfloat16(x - __bfloat162float(h));
}

// ---------------- weight pre-conversion ----------------
__global__ void split_plain(const float* __restrict__ in,
                            __nv_bfloat16* __restrict__ oh,
                            __nv_bfloat16* __restrict__ ol, int n) {
    for (int i = blockIdx.x * blockDim.x + threadIdx.x; i < n; i += gridDim.x * blockDim.x) {
        __nv_bfloat16 h, l; split2(in[i], h, l);
        oh[i] = h; ol[i] = l;
    }
}

// in: [z][K=C][N=C] fp32 -> out: [z][N][K] bf16 hi/lo
__global__ void split_transpose(const float* __restrict__ in,
                                __nv_bfloat16* __restrict__ oh,
                                __nv_bfloat16* __restrict__ ol) {
    __shared__ float t[32][33];
    const size_t zoff = (size_t)blockIdx.z * C * C;
    int k0 = blockIdx.y * 32, n0 = blockIdx.x * 32;
    int tx = threadIdx.x, ty = threadIdx.y;     // 32 x 8
    #pragma unroll
    for (int i = 0; i < 32; i += 8)
        t[ty + i][tx] = in[zoff + (size_t)(k0 + ty + i) * C + n0 + tx];
    __syncthreads();
    #pragma unroll
    for (int i = 0; i < 32; i += 8) {
        float v = t[tx][ty + i];
        __nv_bfloat16 h, l; split2(v, h, l);
        size_t o = zoff + (size_t)(n0 + ty + i) * C + k0 + tx;
        oh[o] = h; ol[o] = l;
    }
}

// ---------------- tensor-core GEMM, split-bf16 (3-term) ----------------
// C = act(A @ B^T + bias). A:[M,K] fp32 (split in loader). B: precomputed bf16 hi/lo [N,K].
// blockIdx.x = M-tile, blockIdx.y = N-tile, blockIdx.z = batch.
constexpr int PAD = 40;   // bf16 elems per smem row -> conflict-free fragment loads

template<bool ACT_GELU, bool WINNER>
__global__ void __launch_bounds__(256, 1)
tgemm(const float* __restrict__ A, size_t astride,
      const __nv_bfloat16* __restrict__ Bhg, const __nv_bfloat16* __restrict__ Blg,
      size_t bstride,
      const float* __restrict__ bias, size_t biasstride,
      float* __restrict__ Cm, size_t cstride,
      int M, int N, int K,
      const int* __restrict__ winner, float* __restrict__ C2) {
    __shared__ __nv_bfloat16 Ah[128][PAD], Al[128][PAD], Bh[128][PAD], Bl[128][PAD];

    int z = blockIdx.z;
    A   += (size_t)z * astride;
    Bhg += (size_t)z * bstride;
    Blg += (size_t)z * bstride;
    if (bias) bias += (size_t)z * biasstride;
    Cm  += (size_t)z * cstride;

    int tid = threadIdx.x;
    int row0 = blockIdx.x * 128;
    int col0 = blockIdx.y * 128;
    int warp = tid >> 5, lane = tid & 31;
    int wm = warp >> 2, wn = warp & 3;           // 2 x 4 warps
    int lr = lane >> 2, lc = lane & 3;

    float acc[4][4][4];
    #pragma unroll
    for (int i = 0; i < 4; i++)
        #pragma unroll
        for (int j = 0; j < 4; j++)
            #pragma unroll
            for (int r = 0; r < 4; r++) acc[i][j][r] = 0.f;

    for (int k0 = 0; k0 < K; k0 += 32) {
        // ---- A tile 128x32: fp32 -> hi/lo bf16 ----
        #pragma unroll
        for (int i = 0; i < 4; i++) {
            int id = tid + i * 256;            // 1024 float4
            int r = id >> 3, c4 = (id & 7) * 4;
            float4 v = *(const float4*)(A + (size_t)(row0 + r) * K + k0 + c4);
            __nv_bfloat16 h0,h1,h2,h3,l0,l1,l2,l3;
            split2(v.x,h0,l0); split2(v.y,h1,l1); split2(v.z,h2,l2); split2(v.w,h3,l3);
            *(unsigned*)&Ah[r][c4]     = pack_bf16(h0,h1);
            *(unsigned*)&Ah[r][c4 + 2] = pack_bf16(h2,h3);
            *(unsigned*)&Al[r][c4]     = pack_bf16(l0,l1);
            *(unsigned*)&Al[r][c4 + 2] = pack_bf16(l2,l3);
        }
        // ---- B tile 128x32: direct bf16 hi/lo loads ([N,K] layout) ----
        #pragma unroll
        for (int i = 0; i < 2; i++) {
            int id = tid + i * 256;            // 512 float4 (8 bf16) per array
            int r = id >> 2, c8 = (id & 3) * 8;
            *(float4*)&Bh[r][c8] = *(const float4*)(Bhg + (size_t)(col0 + r) * K + k0 + c8);
            *(float4*)&Bl[r][c8] = *(const float4*)(Blg + (size_t)(col0 + r) * K + k0 + c8);
        }
        __syncthreads();

        #pragma unroll
        for (int ks = 0; ks < 2; ks++) {
            int kk = ks * 16;
            unsigned ah[4][4], al[4][4];
            #pragma unroll
            for (int mt = 0; mt < 4; mt++) {
                int m = wm * 64 + mt * 16 + lr;
                ah[mt][0] = *(const unsigned*)&Ah[m    ][kk     + lc*2];
                ah[mt][1] = *(const unsigned*)&Ah[m + 8][kk     + lc*2];
                ah[mt][2] = *(const unsigned*)&Ah[m    ][kk + 8 + lc*2];
                ah[mt][3] = *(const unsigned*)&Ah[m + 8][kk + 8 + lc*2];
                al[mt][0] = *(const unsigned*)&Al[m    ][kk     + lc*2];
                al[mt][1] = *(const unsigned*)&Al[m + 8][kk     + lc*2];
                al[mt][2] = *(const unsigned*)&Al[m    ][kk + 8 + lc*2];
                al[mt][3] = *(const unsigned*)&Al[m + 8][kk + 8 + lc*2];
            }
            unsigned bh[4][2], bl[4][2];
            #pragma unroll
            for (int nt = 0; nt < 4; nt++) {
                int n = wn * 32 + nt * 8 + lr;
                bh[nt][0] = *(const unsigned*)&Bh[n][kk     + lc*2];
                bh[nt][1] = *(const unsigned*)&Bh[n][kk + 8 + lc*2];
                bl[nt][0] = *(const unsigned*)&Bl[n][kk     + lc*2];
                bl[nt][1] = *(const unsigned*)&Bl[n][kk + 8 + lc*2];
            }
            #pragma unroll
            for (int mt = 0; mt < 4; mt++)
                #pragma unroll
                for (int nt = 0; nt < 4; nt++) {
                    mma_bf16(acc[mt][nt], ah[mt], bh[nt]);
                    mma_bf16(acc[mt][nt], ah[mt], bl[nt]);
                    mma_bf16(acc[mt][nt], al[mt], bh[nt]);
                }
        }
        __syncthreads();
    }

    // ---- epilogue ----
    #pragma unroll
    for (int mt = 0; mt < 4; mt++) {
        int r0 = row0 + wm * 64 + mt * 16 + lr;
        int w0 = -2, w1 = -2;
        if (WINNER) { w0 = winner[r0]; w1 = winner[r0 + 8]; }
        #pragma unroll
        for (int nt = 0; nt < 4; nt++) {
            int c = col0 + wn * 32 + nt * 8 + lc * 2;
            float v0 = acc[mt][nt][0], v1 = acc[mt][nt][1];
            float v2 = acc[mt][nt][2], v3 = acc[mt][nt][3];
            if (bias) {
                float b0v = bias[c], b1v = bias[c + 1];
                v0 += b0v; v1 += b1v; v2 += b0v; v3 += b1v;
            }
            if (ACT_GELU) { v0 = gelu_f(v0); v1 = gelu_f(v1); v2 = gelu_f(v2); v3 = gelu_f(v3); }
            *(float2*)&Cm[(size_t)r0 * N + c]       = make_float2(v0, v1);
            *(float2*)&Cm[(size_t)(r0 + 8) * N + c] = make_float2(v2, v3);
            if (WINNER) {
                if (w0 == z) *(float2*)&C2[(size_t)r0 * N + c]       = make_float2(v0, v1);
                if (w1 == z) *(float2*)&C2[(size_t)(r0 + 8) * N + c] = make_float2(v2, v3);
            }
        }
    }
}

// ---------------- block reduction ----------------
__device__ __forceinline__ float blk_sum(float v) {
    __shared__ float sh[8];
    __syncthreads();
    #pragma unroll
    for (int o = 16; o > 0; o >>= 1) v += __shfl_down_sync(0xffffffffu, v, o);
    if ((threadIdx.x & 31) == 0) sh[threadIdx.x >> 5] = v;
    __syncthreads();
    if (threadIdx.x == 0) {
        float t = 0.f;
        #pragma unroll
        for (int i = 0; i < 8; i++) t += sh[i];
        sh[0] = t;
    }
    __syncthreads();
    return sh[0];
}

// ---------------- embedding + positional encoding ----------------
__global__ void embed_kernel(const int* __restrict__ ids,
                             const float* __restrict__ emb,
                             float* __restrict__ x) {
    int t = blockIdx.x;
    int pos = t & (T - 1);
    int id = ids[t];
    const float* erow = emb + (size_t)id * C;
    float* xrow = x + (size_t)t * C;
    const float nl = -9.210340371976184f / (float)C;
    #pragma unroll
    for (int i = 0; i < 4; i++) {
        int c = threadIdx.x + i * 256;
        int i2 = c & ~1;
        float freq = expf((float)i2 * nl);
        float val = (float)pos * freq;
        float pe = (c & 1) ? cosf(val) : sinf(val);
        xrow[c] = erow[c] + pe;
    }
}

// ---------------- fused attention (fp32 SIMT) ----------------
constexpr int SSTRIDE = 513;
constexpr int ATTN_SMEM = (64 * SSTRIDE + 2 * 64 * 68) * 4;   // 166,144 B

__global__ void __launch_bounds__(256)
attn_fused(const float* __restrict__ qkv, float* __restrict__ abuf) {
    extern __shared__ float sm[];
    float* Sc = sm;
    float* Qs = sm + 64 * SSTRIDE;
    float* KV = Qs + 64 * 68;

    int bh = blockIdx.y;
    int b = bh >> 4, h = bh & 15;
    int t0 = blockIdx.x * 64;
    const float* qb = qkv + (size_t)b * T * (3 * C) + h * D;
    const float* kb = qb + C;
    const float* vb = qb + 2 * C;

    int tid = threadIdx.x;
    int row = tid >> 2, cb = (tid & 3) * 16;
    int ty = tid >> 4, tx = tid & 15;

    #pragma unroll
    for (int j = 0; j < 4; j++) {
        float4 q4 = *(const float4*)(qb + (size_t)(t0 + row) * (3 * C) + cb + j * 4);
        Qs[(cb + j * 4 + 0) * 68 + row] = q4.x;
        Qs[(cb + j * 4 + 1) * 68 + row] = q4.y;
        Qs[(cb + j * 4 + 2) * 68 + row] = q4.z;
        Qs[(cb + j * 4 + 3) * 68 + row] = q4.w;
    }

    for (int s0 = 0; s0 < T; s0 += 64) {
        __syncthreads();
        #pragma unroll
        for (int j = 0; j < 4; j++) {
            float4 k4 = *(const float4*)(kb + (size_t)(s0 + row) * (3 * C) + cb + j * 4);
            KV[(cb + j * 4 + 0) * 68 + row] = k4.x;
            KV[(cb + j * 4 + 1) * 68 + row] = k4.y;
            KV[(cb + j * 4 + 2) * 68 + row] = k4.z;
            KV[(cb + j * 4 + 3) * 68 + row] = k4.w;
        }
        __syncthreads();
        float acc[4][4] = {};
        #pragma unroll 4
        for (int d = 0; d < 64; d++) {
            float a_[4], b_[4];
            #pragma unroll
            for (int i = 0; i < 4; i++) a_[i] = Qs[d * 68 + ty * 4 + i];
            #pragma unroll
            for (int j = 0; j < 4; j++) b_[j] = KV[d * 68 + tx * 4 + j];
            #pragma unroll
            for (int i = 0; i < 4; i++)
                #pragma unroll
                for (int j = 0; j < 4; j++) acc[i][j] += a_[i] * b_[j];
        }
        #pragma unroll
        for (int i = 0; i < 4; i++)
            #pragma unroll
            for (int j = 0; j < 4; j++)
                Sc[(ty * 4 + i) * SSTRIDE + s0 + tx * 4 + j] = acc[i][j] * 0.125f;
    }
    __syncthreads();

    int warp = tid >> 5, lane = tid & 31;
    #pragma unroll
    for (int it = 0; it < 8; it++) {
        int r = it * 8 + warp;
        float* srow = Sc + r * SSTRIDE;
        float v[16];
        float m = -1e30f;
        #pragma unroll
        for (int k = 0; k < 16; k++) { v[k] = srow[lane + 32 * k]; m = fmaxf(m, v[k]); }
        #pragma unroll
        for (int o = 16; o > 0; o >>= 1) m = fmaxf(m, __shfl_xor_sync(0xffffffffu, m, o));
        float s = 0.f;
        #pragma unroll
        for (int k = 0; k < 16; k++) { v[k] = expf(v[k] - m); s += v[k]; }
        #pragma unroll
        for (int o = 16; o > 0; o >>= 1) s += __shfl_xor_sync(0xffffffffu, s, o);
        float inv = 1.0f / s;
        #pragma unroll
        for (int k = 0; k < 16; k++) srow[lane + 32 * k] = v[k] * inv;
    }

    float acc[4][4] = {};
    for (int s0 = 0; s0 < T; s0 += 64) {
        __syncthreads();
        #pragma unroll
        for (int j = 0; j < 4; j++) {
            float4 v4 = *(const float4*)(vb + (size_t)(s0 + row) * (3 * C) + cb + j * 4);
            *(float4*)&KV[row * 68 + cb + j * 4] = v4;
        }
        __syncthreads();
        #pragma unroll 4
        for (int s = 0; s < 64; s++) {
            float a_[4], b_[4];
            #pragma unroll
            for (int i = 0; i < 4; i++) a_[i] = Sc[(ty * 4 + i) * SSTRIDE + s0 + s];
            #pragma unroll
            for (int j = 0; j < 4; j++) b_[j] = KV[s * 68 + tx * 4 + j];
            #pragma unroll
            for (int i = 0; i < 4; i++)
                #pragma unroll
                for (int j = 0; j < 4; j++) acc[i][j] += a_[i] * b_[j];
        }
    }
    #pragma unroll
    for (int i = 0; i < 4; i++)
        #pragma unroll
        for (int j = 0; j < 4; j++)
            abuf[((size_t)b * T + t0 + ty * 4 + i) * C + h * D + tx * 4 + j] = acc[i][j];
}

// ---------------- LayerNorm ----------------
__global__ void __launch_bounds__(256)
add_ln(const float* __restrict__ x, const float* __restrict__ add,
       const float* __restrict__ g, const float* __restrict__ b,
       float* __restrict__ out) {
    int t = blockIdx.x;
    size_t base = (size_t)t * C;
    float v[4];
    #pragma unroll
    for (int i = 0; i < 4; i++) {
        int c = threadIdx.x + i * 256;
        v[i] = x[base + c] + (add ? add[base + c] : 0.f);
    }
    float mean = blk_sum(v[0] + v[1] + v[2] + v[3]) * (1.0f / C);
    float sq = 0.f;
    #pragma unroll
    for (int i = 0; i < 4; i++) { float d = v[i] - mean; sq += d * d; }
    float var = blk_sum(sq) * (1.0f / C);
    float rstd = rsqrtf(var + 1e-5f);
    #pragma unroll
    for (int i = 0; i < 4; i++) {
        int c = threadIdx.x + i * 256;
        out[base + c] = (v[i] - mean) * rstd * g[c] + b[c];
    }
}

// ---------------- router ----------------
__global__ void __launch_bounds__(256)
router_kernel(const float* __restrict__ x, const float* __restrict__ rw,
              const float* __restrict__ rb,
              int* __restrict__ win, int* __restrict__ maskb,
              int* __restrict__ cnt) {
    int t = blockIdx.x;
    int wid = threadIdx.x >> 5, lane = threadIdx.x & 31;
    const float* xr = x + (size_t)t * C;
    const float* w = rw + (size_t)wid * C;
    float s = 0.f;
    for (int c = lane; c < C; c += 32) s += xr[c] * w[c];
    #pragma unroll
    for (int o = 16; o > 0; o >>= 1) s += __shfl_down_sync(0xffffffffu, s, o);
    __shared__ float logits[E];
    if (lane == 0) logits[wid] = s + rb[wid];
    __syncthreads();
    if (threadIdx.x == 0) {
        int i0 = 0; float b0 = logits[0];
        #pragma unroll
        for (int e = 1; e < E; e++) if (logits[e] > b0) { b0 = logits[e]; i0 = e; }
        int i1 = -1; float b1 = -1e30f;
        #pragma unroll
        for (int e = 0; e < E; e++) if (e != i0 && logits[e] > b1) { b1 = logits[e]; i1 = e; }
        int wnr = i0 > i1 ? i0 : i1;
        win[t] = wnr;
        maskb[t] = (1 << i0) | (1 << i1);
        atomicAdd(&cnt[i0], 1);
        atomicAdd(&cnt[i1], 1);
    }
}

__global__ void zero_small(int* c, float* es) {
    if (blockIdx.x == 0 && threadIdx.x < E) c[threadIdx.x] = 0;
    for (int i = blockIdx.x * blockDim.x + threadIdx.x; i < E * C; i += gridDim.x * blockDim.x)
        es[i] = 0.f;
}

// ---------------- per-expert masked partial sums (batched over z) ----------------
__global__ void __launch_bounds__(256)
expert_reduce(const float* __restrict__ y, const int* __restrict__ maskb,
              float* __restrict__ esum) {
    int e = blockIdx.z;
    const float* ye = y + (size_t)e * BT * C;
    int c = blockIdx.x * 256 + threadIdx.x;
    int t0 = blockIdx.y * 64;
    float s = 0.f;
    #pragma unroll 4
    for (int t = t0; t < t0 + 64; t++) {
        if ((maskb[t] >> e) & 1) s += ye[(size_t)t * C + c];
    }
    atomicAdd(&esum[e * C + c], s);
}

// ---------------- MoE finalize + LN ----------------
__global__ void __launch_bounds__(256)
moe_ln(float* __restrict__ x, const float* __restrict__ moe,
       const float* __restrict__ esum, const int* __restrict__ win,
       const int* __restrict__ cnt, float inv_cache,
       const float* __restrict__ g, const float* __restrict__ b) {
    int t = blockIdx.x;
    size_t base = (size_t)t * C;
    int w = win[t];
    float cs = inv_cache / fmaxf((float)cnt[w], 1.0f);
    float v[4];
    #pragma unroll
    for (int i = 0; i < 4; i++) {
        int c = threadIdx.x + i * 256;
        v[i] = x[base + c] + moe[base + c] + esum[w * C + c] * cs;
    }
    float mean = blk_sum(v[0] + v[1] + v[2] + v[3]) * (1.0f / C);
    float sq = 0.f;
    #pragma unroll
    for (int i = 0; i < 4; i++) { float d = v[i] - mean; sq += d * d; }
    float var = blk_sum(sq) * (1.0f / C);
    float rstd = rsqrtf(var + 1e-5f);
    #pragma unroll
    for (int i = 0; i < 4; i++) {
        int c = threadIdx.x + i * 256;
        x[base + c] = (v[i] - mean) * rstd * g[c] + b[c];
    }
}

// ---------------- host launch ----------------
extern "C" void kernel_launch(void* const* d_in, const int* in_sizes, int n_in,
                              void* d_out, int out_size) {
    const int*   ids      = (const int*)  d_in[0];
    const float* emb      = (const float*)d_in[1];
    const float* qkv_w    = (const float*)d_in[2];
    const float* qkv_b    = (const float*)d_in[3];
    const float* out_w    = (const float*)d_in[4];
    const float* out_b    = (const float*)d_in[5];
    const float* ln1_g    = (const float*)d_in[6];
    const float* ln1_b    = (const float*)d_in[7];
    const float* router_w = (const float*)d_in[8];
    const float* router_b = (const float*)d_in[9];
    const float* w1       = (const float*)d_in[10];
    const float* b1       = (const float*)d_in[11];
    const float* w2       = (const float*)d_in[12];
    const float* b2       = (const float*)d_in[13];
    const float* ln2_g    = (const float*)d_in[14];
    const float* ln2_b    = (const float*)d_in[15];
    const float* lnf_g    = (const float*)d_in[16];
    const float* lnf_b    = (const float*)d_in[17];
    const float* head_w   = (const float*)d_in[18];
    float* out = (float*)d_out;

    float *dX, *dQKV, *dABUF, *dTMP, *dH, *dY, *dMOE, *dESUM;
    int *dWIN, *dMASK, *dCNT;
    cudaGetSymbolAddress((void**)&dX, g_x);
    cudaGetSymbolAddress((void**)&dQKV, g_qkv);
    cudaGetSymbolAddress((void**)&dABUF, g_abuf);
    cudaGetSymbolAddress((void**)&dTMP, g_tmp);
    cudaGetSymbolAddress((void**)&dH, g_h);
    cudaGetSymbolAddress((void**)&dY, g_y);
    cudaGetSymbolAddress((void**)&dMOE, g_moe);
    cudaGetSymbolAddress((void**)&dESUM, g_esum);
    cudaGetSymbolAddress((void**)&dWIN, g_win);
    cudaGetSymbolAddress((void**)&dMASK, g_mask);
    cudaGetSymbolAddress((void**)&dCNT, g_cnt);

    __nv_bfloat16 *qwh, *qwl, *owh, *owl, *w1h, *w1l, *w2h, *w2l, *hwh, *hwl;
    cudaGetSymbolAddress((void**)&qwh, s_qkvw_h);
    cudaGetSymbolAddress((void**)&qwl, s_qkvw_l);
    cudaGetSymbolAddress((void**)&owh, s_outw_h);
    cudaGetSymbolAddress((void**)&owl, s_outw_l);
    cudaGetSymbolAddress((void**)&w1h, s_w1_h);
    cudaGetSymbolAddress((void**)&w1l, s_w1_l);
    cudaGetSymbolAddress((void**)&w2h, s_w2_h);
    cudaGetSymbolAddress((void**)&w2l, s_w2_l);
    cudaGetSymbolAddress((void**)&hwh, s_head_h);
    cudaGetSymbolAddress((void**)&hwl, s_head_l);

    cudaFuncSetAttribute(attn_fused, cudaFuncAttributeMaxDynamicSharedMemorySize, ATTN_SMEM);

    // ---- per-launch weight conversion to split-bf16 [N,K] ----
    split_plain<<<4096, 256>>>(qkv_w,  qwh, qwl, NQKVW);
    split_plain<<<2048, 256>>>(out_w,  owh, owl, NOUTW);
    split_plain<<<8192, 256>>>(head_w, hwh, hwl, NHEAD);
    split_transpose<<<dim3(C / 32, C / 32, Ll * E), dim3(32, 8)>>>(w1, w1h, w1l);
    split_transpose<<<dim3(C / 32, C / 32, Ll * E), dim3(32, 8)>>>(w2, w2h, w2l);

    embed_kernel<<<BT, 256>>>(ids, emb, dX);

    for (int l = 0; l < Ll; l++) {
        // QKV: [2048,1024] @ [3072,1024]^T
        tgemm<false, false><<<dim3(BT / 128, 3 * C / 128, 1), 256>>>(
            dX, 0, qwh + (size_t)l * 3 * C * C, qwl + (size_t)l * 3 * C * C, 0,
            qkv_b + (size_t)l * 3 * C, 0, dQKV, 0, BT, 3 * C, C, nullptr, nullptr);

        attn_fused<<<dim3(T / 64, B * Hh), 256, ATTN_SMEM>>>(dQKV, dABUF);

        tgemm<false, false><<<dim3(BT / 128, C / 128, 1), 256>>>(
            dABUF, 0, owh + (size_t)l * C * C, owl + (size_t)l * C * C, 0,
            out_b + (size_t)l * C, 0, dTMP, 0, BT, C, C, nullptr, nullptr);
        add_ln<<<BT, 256>>>(dX, dTMP, ln1_g + (size_t)l * C, ln1_b + (size_t)l * C, dX);

        zero_small<<<8, 1024>>>(dCNT, dESUM);
        router_kernel<<<BT, 256>>>(dX, router_w + (size_t)l * E * C,
                                   router_b + (size_t)l * E, dWIN, dMASK, dCNT);

        // batched experts: z = expert
        size_t wlo = (size_t)l * E * C * C;
        tgemm<true, false><<<dim3(BT / 128, C / 128, E), 256>>>(
            dX, 0, w1h + wlo, w1l + wlo, (size_t)C * C,
            b1 + (size_t)l * E * C, C, dH, (size_t)BT * C,
            BT, C, C, nullptr, nullptr);
        tgemm<false, true><<<dim3(BT / 128, C / 128, E), 256>>>(
            dH, (size_t)BT * C, w2h + wlo, w2l + wlo, (size_t)C * C,
            b2 + (size_t)l * E * C, C, dY, (size_t)BT * C,
            BT, C, C, dWIN, dMOE);
        expert_reduce<<<dim3(C / 256, BT / 64, E), 256>>>(dY, dMASK, dESUM);

        float inv_cache = 1.0f / (float)(128 - 8 * l);
        moe_ln<<<BT, 256>>>(dX, dMOE, dESUM, dWIN, dCNT, inv_cache,
                            ln2_g + (size_t)l * C, ln2_b + (size_t)l * C);
    }

    add_ln<<<BT, 256>>>(dX, nullptr, lnf_g, lnf_b, dTMP);
    tgemm<false, false><<<dim3(BT / 128, Vv / 128, 1), 256>>>(
        dTMP, 0, hwh, hwl, 0, nullptr, 0, out, 0, BT, Vv, C, nullptr, nullptr);
}